// round 13
// baseline (speedup 1.0000x reference)
#include <cuda_runtime.h>
#include <cuda_fp16.h>
#include <math.h>

#define N_NODES_MAX 50000
#define F 64
#define NEG 0.01f
#define CAP 128
#define ASTRIDE 136   // halves per shared row: word stride 68 == 4 mod 32 banks

// ---- scratch ----
__device__ float  g_ssrc[N_NODES_MAX];
__device__ float  g_sdst[N_NODES_MAX];
__device__ int    g_cnt [N_NODES_MAX];
__device__ int2   g_ebuf[N_NODES_MAX * CAP];
__device__ __half g_AH[N_NODES_MAX * 128];   // fp16 feature rows (cols 0-63 used)
__device__ __half g_WH[64 * 128];            // fp16 copy of lin_w

// K1: node attention scores (4 threads/node) + zero cnt + fp16 feature copy
// + one-time fp16 W conversion (first 2048 global threads).
__global__ void k_scores(const float4* __restrict__ feat4,
                         const float*  __restrict__ attw,
                         const float*  __restrict__ lin_w,
                         int n)
{
    int t = blockIdx.x * blockDim.x + threadIdx.x;

    if (t < 2048) {   // convert W: 8192 floats = 2048 float4
        float4 w = __ldg((const float4*)&lin_w[t * 4]);
        __half2 h0 = __floats2half2_rn(w.x, w.y);
        __half2 h1 = __floats2half2_rn(w.z, w.w);
        uint2 u;
        u.x = *(unsigned int*)&h0;
        u.y = *(unsigned int*)&h1;
        *(uint2*)&g_WH[t * 4] = u;
    }

    int node = t >> 2;
    int p = t & 3;
    if (node >= n) return;

    float as = 0.f, ad = 0.f;
#pragma unroll
    for (int j = 0; j < 4; j++) {
        int q = p * 4 + j;
        float4 f = feat4[node * 16 + q];
        float4 wa = __ldg((const float4*)&attw[q * 4]);
        float4 wb = __ldg((const float4*)&attw[64 + q * 4]);
        as += f.x * wa.x + f.y * wa.y + f.z * wa.z + f.w * wa.w;
        ad += f.x * wb.x + f.y * wb.y + f.z * wb.z + f.w * wb.w;
        __half2 h0 = __floats2half2_rn(f.x, f.y);
        __half2 h1 = __floats2half2_rn(f.z, f.w);
        uint2 u;
        u.x = *(unsigned int*)&h0;
        u.y = *(unsigned int*)&h1;
        *(uint2*)&g_AH[node * 128 + q * 4] = u;
    }
    as += __shfl_xor_sync(0xffffffffu, as, 1);
    as += __shfl_xor_sync(0xffffffffu, as, 2);
    ad += __shfl_xor_sync(0xffffffffu, ad, 1);
    ad += __shfl_xor_sync(0xffffffffu, ad, 2);

    if (p == 0) {
        g_ssrc[node] = as;
        g_sdst[node] = ad;
        g_cnt[node]  = 0;
    }
}

// K2: per-edge exp score + bucket scatter.
__global__ void k_scatter(const int* __restrict__ src,
                          const int* __restrict__ dst,
                          int E)
{
    int e = blockIdx.x * blockDim.x + threadIdx.x;
    if (e >= E) return;
    int s = src[e], d = dst[e];
    float v = g_ssrc[s] + g_sdst[d];
    v = v > 0.f ? v : NEG * v;
    float ex = __expf(v);
    int slot = atomicAdd(&g_cnt[d], 1);
    if (slot < CAP)
        g_ebuf[(size_t)d * CAP + slot] = make_int2(s, __float_as_int(ex));
}

__device__ __forceinline__ void acc_one(float4& acc, float& dsum,
                                        uint2 u, float xw)
{
    float2 a = __half22float2(*(__half2*)&u.x);
    float2 b = __half22float2(*(__half2*)&u.y);
    acc.x += xw * a.x;
    acc.y += xw * a.y;
    acc.z += xw * b.x;
    acc.w += xw * b.y;
    dsum += xw;
}

// ---- HMMA m16n8k16 f16 x f16 -> f32 ----
__device__ __forceinline__ void mma16816(float& c0, float& c1, float& c2, float& c3,
                                         unsigned a0, unsigned a1, unsigned a2, unsigned a3,
                                         unsigned b0, unsigned b1)
{
    asm volatile("mma.sync.aligned.m16n8k16.row.col.f32.f16.f16.f32 "
                 "{%0,%1,%2,%3}, {%4,%5,%6,%7}, {%8,%9}, {%0,%1,%2,%3};"
                 : "+f"(c0), "+f"(c1), "+f"(c2), "+f"(c3)
                 : "r"(a0), "r"(a1), "r"(a2), "r"(a3), "r"(b0), "r"(b1));
}

// K3 (fused agg + output GEMM): 1024 threads = 32 warps per block, 64 nodes.
// Agg: R10 loop + software-pipelined entry prefetch (next window's 4 entry
//   loads issue before current window's gathers are consumed).
// GEMM: 32 warps each compute one m16n8k16 tile of h = relu(A @ W^T + b).
__global__ void __launch_bounds__(1024) k_fused(
                      const float* __restrict__ lin_b,
                      float*       __restrict__ out,     // [n, 64]
                      int n)
{
    __shared__ __align__(16) __half W_s[64 * ASTRIDE];
    __shared__ __align__(16) __half A_s[64 * ASTRIDE];
    __shared__ float b_s[64];

    int tid = threadIdx.x;
    int base = blockIdx.x * 64;

    // stage W (fp16, 16KB): 1024 threads x 1 uint4 (8 halves)
    {
        int o = tid >> 4, c = tid & 15;
        uint4 w = *(const uint4*)&g_WH[o * 128 + c * 8];
        *(uint4*)&W_s[o * ASTRIDE + c * 8] = w;
    }
    if (tid < 64) b_s[tid] = __ldg(&lin_b[tid]);
    // stage feature half of A tile: 64 rows x 8 uint4
    if (tid < 512) {
        int r = tid >> 3, c = tid & 7;
        int node = base + r;
        if (node >= n) node = n - 1;
        uint4 v = *(const uint4*)&g_AH[(size_t)node * 128 + c * 8];
        *(uint4*)&A_s[r * ASTRIDE + c * 8] = v;
    }

    int warp = tid >> 5, lane = tid & 31;
    int half = lane >> 4;
    int q = lane & 15;
    const uint2* ah = (const uint2*)g_AH;

#pragma unroll
    for (int pass = 0; pass < 2; pass++) {
        int row = warp + pass * 32;
        int node = base + row;
        if (node < n) {
            int deg = g_cnt[node];
            if (deg > CAP) deg = CAP;
            const int2* eb = &g_ebuf[(size_t)node * CAP];

            float4 acc = make_float4(0.f, 0.f, 0.f, 0.f);
            float dsum = 0.f;

            int j = half;
            // preload first window's entries (safe: indices < CAP)
            int2 e0 = __ldg(&eb[j]);
            int2 e1 = __ldg(&eb[j + 2]);
            int2 e2 = __ldg(&eb[j + 4]);
            int2 e3 = __ldg(&eb[j + 6]);

            while (j + 6 < deg) {
                // issue gathers for current window
                uint2 u0 = ah[e0.x * 32 + q];
                uint2 u1 = ah[e1.x * 32 + q];
                uint2 u2 = ah[e2.x * 32 + q];
                uint2 u3 = ah[e3.x * 32 + q];
                // prefetch next window's entries (indices < CAP always)
                int jn = j + 8;
                int2 f0 = __ldg(&eb[jn]);
                int2 f1 = __ldg(&eb[jn + 2]);
                int2 f2 = __ldg(&eb[jn + 4]);
                int2 f3 = __ldg(&eb[jn + 6]);
                // accumulate current window
                acc_one(acc, dsum, u0, __int_as_float(e0.y));
                acc_one(acc, dsum, u1, __int_as_float(e1.y));
                acc_one(acc, dsum, u2, __int_as_float(e2.y));
                acc_one(acc, dsum, u3, __int_as_float(e3.y));
                e0 = f0; e1 = f1; e2 = f2; e3 = f3;
                j = jn;
            }
            while (j < deg) {
                int2 t0 = __ldg(&eb[j]);
                uint2 u0 = ah[t0.x * 32 + q];
                acc_one(acc, dsum, u0, __int_as_float(t0.y));
                j += 2;
            }

            acc.x += __shfl_xor_sync(0xffffffffu, acc.x, 16);
            acc.y += __shfl_xor_sync(0xffffffffu, acc.y, 16);
            acc.z += __shfl_xor_sync(0xffffffffu, acc.z, 16);
            acc.w += __shfl_xor_sync(0xffffffffu, acc.w, 16);
            dsum  += __shfl_xor_sync(0xffffffffu, dsum, 16);

            if (half == 0) {
                float inv = dsum > 0.f ? 1.f / dsum : 0.f;
                __half2 h0 = __floats2half2_rn(acc.x * inv, acc.y * inv);
                __half2 h1 = __floats2half2_rn(acc.z * inv, acc.w * inv);
                uint2 u;
                u.x = *(unsigned int*)&h0;
                u.y = *(unsigned int*)&h1;
                *(uint2*)&A_s[row * ASTRIDE + 64 + q * 4] = u;
            }
        }
    }

    __syncthreads();

    // GEMM: warp -> (m-tile r, n-tile i)
    {
        int r = warp & 3, i = warp >> 2;
        int g = lane >> 2, j = lane & 3;
        int arow = r * 16 + g;

        float c0 = 0.f, c1 = 0.f, c2 = 0.f, c3 = 0.f;
#pragma unroll
        for (int s = 0; s < 8; s++) {
            int k0 = 16 * s;
            unsigned a0 = *(const unsigned*)&A_s[arow * ASTRIDE + k0 + 2 * j];
            unsigned a1 = *(const unsigned*)&A_s[(arow + 8) * ASTRIDE + k0 + 2 * j];
            unsigned a2 = *(const unsigned*)&A_s[arow * ASTRIDE + k0 + 8 + 2 * j];
            unsigned a3 = *(const unsigned*)&A_s[(arow + 8) * ASTRIDE + k0 + 8 + 2 * j];
            unsigned b0 = *(const unsigned*)&W_s[(8 * i + g) * ASTRIDE + k0 + 2 * j];
            unsigned b1 = *(const unsigned*)&W_s[(8 * i + g) * ASTRIDE + k0 + 8 + 2 * j];
            mma16816(c0, c1, c2, c3, a0, a1, a2, a3, b0, b1);
        }

        int c = 8 * i + 2 * j;
        float2 bb = *(const float2*)&b_s[c];
        int n0 = base + arow;
        int n1 = n0 + 8;
        if (n0 < n) {
            float2 r0;
            r0.x = fmaxf(c0 + bb.x, 0.f);
            r0.y = fmaxf(c1 + bb.y, 0.f);
            *(float2*)&out[(size_t)n0 * 64 + c] = r0;
        }
        if (n1 < n) {
            float2 r1;
            r1.x = fmaxf(c2 + bb.x, 0.f);
            r1.y = fmaxf(c3 + bb.y, 0.f);
            *(float2*)&out[(size_t)n1 * 64 + c] = r1;
        }
    }
}

extern "C" void kernel_launch(void* const* d_in, const int* in_sizes, int n_in,
                              void* d_out, int out_size)
{
    const float* feature = (const float*)d_in[0];   // [N, 64]
    const float* attn_w  = (const float*)d_in[1];   // [128, 1]
    const float* lin_w   = (const float*)d_in[2];   // [64, 128]
    const float* lin_b   = (const float*)d_in[3];   // [64]
    const int*   src     = (const int*)d_in[4];     // [E]
    const int*   dst     = (const int*)d_in[5];     // [E]

    int n = in_sizes[0] / F;
    int E = in_sizes[4];

    const float4* feat4 = (const float4*)feature;

    {   // K1: scores + cnt reset + fp16 feature & W conversion
        int threads = 256;
        long long total = (long long)n * 4;
        int blocks = (int)((total + threads - 1) / threads);
        k_scores<<<blocks, threads>>>(feat4, attn_w, lin_w, n);
    }
    {   // K2: edge scatter
        int threads = 256;
        int blocks = (E + threads - 1) / threads;
        k_scatter<<<blocks, threads>>>(src, dst, E);
    }
    {   // K3: fused aggregation + output GEMM (64 nodes / 1024-thread block)
        int blocks = (n + 63) / 64;
        k_fused<<<blocks, 1024>>>(lin_b, (float*)d_out, n);
    }
}

// round 14
// speedup vs baseline: 1.1492x; 1.1492x over previous
#include <cuda_runtime.h>
#include <cuda_fp16.h>
#include <math.h>

#define N_NODES_MAX 50000
#define F 64
#define NEG 0.01f
#define CAP 128
#define ASTRIDE 136   // halves per shared row: word stride 68 == 4 mod 32 banks
#define NPB 32        // nodes per fused block
#define FTHREADS 512

// ---- scratch ----
__device__ float  g_ssrc[N_NODES_MAX];
__device__ float  g_sdst[N_NODES_MAX];
__device__ int    g_cnt [N_NODES_MAX];
__device__ int2   g_ebuf[N_NODES_MAX * CAP];
__device__ __half g_AH[N_NODES_MAX * 128];   // fp16 feature rows (cols 0-63 used)
__device__ __half g_WH[64 * 128];            // fp16 copy of lin_w

// K1: node attention scores (4 threads/node) + zero cnt + fp16 feature copy
// + one-time fp16 W conversion (first 2048 global threads).
__global__ void k_scores(const float4* __restrict__ feat4,
                         const float*  __restrict__ attw,
                         const float*  __restrict__ lin_w,
                         int n)
{
    int t = blockIdx.x * blockDim.x + threadIdx.x;

    if (t < 2048) {   // convert W: 8192 floats = 2048 float4
        float4 w = __ldg((const float4*)&lin_w[t * 4]);
        __half2 h0 = __floats2half2_rn(w.x, w.y);
        __half2 h1 = __floats2half2_rn(w.z, w.w);
        uint2 u;
        u.x = *(unsigned int*)&h0;
        u.y = *(unsigned int*)&h1;
        *(uint2*)&g_WH[t * 4] = u;
    }

    int node = t >> 2;
    int p = t & 3;
    if (node >= n) return;

    float as = 0.f, ad = 0.f;
#pragma unroll
    for (int j = 0; j < 4; j++) {
        int q = p * 4 + j;
        float4 f = feat4[node * 16 + q];
        float4 wa = __ldg((const float4*)&attw[q * 4]);
        float4 wb = __ldg((const float4*)&attw[64 + q * 4]);
        as += f.x * wa.x + f.y * wa.y + f.z * wa.z + f.w * wa.w;
        ad += f.x * wb.x + f.y * wb.y + f.z * wb.z + f.w * wb.w;
        __half2 h0 = __floats2half2_rn(f.x, f.y);
        __half2 h1 = __floats2half2_rn(f.z, f.w);
        uint2 u;
        u.x = *(unsigned int*)&h0;
        u.y = *(unsigned int*)&h1;
        *(uint2*)&g_AH[node * 128 + q * 4] = u;
    }
    as += __shfl_xor_sync(0xffffffffu, as, 1);
    as += __shfl_xor_sync(0xffffffffu, as, 2);
    ad += __shfl_xor_sync(0xffffffffu, ad, 1);
    ad += __shfl_xor_sync(0xffffffffu, ad, 2);

    if (p == 0) {
        g_ssrc[node] = as;
        g_sdst[node] = ad;
        g_cnt[node]  = 0;
    }
}

// K2: per-edge exp score + bucket scatter.
__global__ void k_scatter(const int* __restrict__ src,
                          const int* __restrict__ dst,
                          int E)
{
    int e = blockIdx.x * blockDim.x + threadIdx.x;
    if (e >= E) return;
    int s = src[e], d = dst[e];
    float v = g_ssrc[s] + g_sdst[d];
    v = v > 0.f ? v : NEG * v;
    float ex = __expf(v);
    int slot = atomicAdd(&g_cnt[d], 1);
    if (slot < CAP)
        g_ebuf[(size_t)d * CAP + slot] = make_int2(s, __float_as_int(ex));
}

__device__ __forceinline__ void acc_one(float4& acc, float& dsum,
                                        uint2 u, float xw)
{
    float2 a = __half22float2(*(__half2*)&u.x);
    float2 b = __half22float2(*(__half2*)&u.y);
    acc.x += xw * a.x;
    acc.y += xw * a.y;
    acc.z += xw * b.x;
    acc.w += xw * b.y;
    dsum += xw;
}

// ---- HMMA m16n8k16 f16 x f16 -> f32 ----
__device__ __forceinline__ void mma16816(float& c0, float& c1, float& c2, float& c3,
                                         unsigned a0, unsigned a1, unsigned a2, unsigned a3,
                                         unsigned b0, unsigned b1)
{
    asm volatile("mma.sync.aligned.m16n8k16.row.col.f32.f16.f16.f32 "
                 "{%0,%1,%2,%3}, {%4,%5,%6,%7}, {%8,%9}, {%0,%1,%2,%3};"
                 : "+f"(c0), "+f"(c1), "+f"(c2), "+f"(c3)
                 : "r"(a0), "r"(a1), "r"(a2), "r"(a3), "r"(b0), "r"(b1));
}

// K3 (fused agg + output GEMM): 512 threads = 16 warps per block, 32 nodes.
// 2 blocks co-resident per SM -> one block's agg hides the other's sync/GEMM.
// Agg: exact R10 loop (no prefetch, no shfl fan-out; fits registers).
// GEMM: 16 warps each compute one m16n8k16 tile (2 m-tiles x 8 n-tiles).
__global__ void __launch_bounds__(FTHREADS, 2) k_fused(
                      const float* __restrict__ lin_b,
                      float*       __restrict__ out,     // [n, 64]
                      int n)
{
    __shared__ __align__(16) __half W_s[64 * ASTRIDE];
    __shared__ __align__(16) __half A_s[NPB * ASTRIDE];
    __shared__ float b_s[64];

    int tid = threadIdx.x;
    int base = blockIdx.x * NPB;

    // stage W (fp16, 16KB): 2 uint4 per thread
    for (int idx = tid; idx < 64 * 16; idx += FTHREADS) {
        int o = idx >> 4, c = idx & 15;
        uint4 w = *(const uint4*)&g_WH[o * 128 + c * 8];
        *(uint4*)&W_s[o * ASTRIDE + c * 8] = w;
    }
    if (tid < 64) b_s[tid] = __ldg(&lin_b[tid]);
    // stage feature half of A tile: 32 rows x 8 uint4
    if (tid < NPB * 8) {
        int r = tid >> 3, c = tid & 7;
        int node = base + r;
        if (node >= n) node = n - 1;
        uint4 v = *(const uint4*)&g_AH[(size_t)node * 128 + c * 8];
        *(uint4*)&A_s[r * ASTRIDE + c * 8] = v;
    }

    int warp = tid >> 5, lane = tid & 31;
    int half = lane >> 4;
    int q = lane & 15;
    const uint2* ah = (const uint2*)g_AH;

#pragma unroll
    for (int pass = 0; pass < 2; pass++) {
        int row = warp + pass * 16;
        int node = base + row;
        if (node < n) {
            int deg = g_cnt[node];
            if (deg > CAP) deg = CAP;
            const int2* eb = &g_ebuf[(size_t)node * CAP];

            float4 acc = make_float4(0.f, 0.f, 0.f, 0.f);
            float dsum = 0.f;

            int j = half;
            while (j + 6 < deg) {
                int2 e0 = __ldg(&eb[j]);
                int2 e1 = __ldg(&eb[j + 2]);
                int2 e2 = __ldg(&eb[j + 4]);
                int2 e3 = __ldg(&eb[j + 6]);
                uint2 u0 = ah[e0.x * 32 + q];
                uint2 u1 = ah[e1.x * 32 + q];
                uint2 u2 = ah[e2.x * 32 + q];
                uint2 u3 = ah[e3.x * 32 + q];
                acc_one(acc, dsum, u0, __int_as_float(e0.y));
                acc_one(acc, dsum, u1, __int_as_float(e1.y));
                acc_one(acc, dsum, u2, __int_as_float(e2.y));
                acc_one(acc, dsum, u3, __int_as_float(e3.y));
                j += 8;
            }
            while (j < deg) {
                int2 e0 = __ldg(&eb[j]);
                uint2 u0 = ah[e0.x * 32 + q];
                acc_one(acc, dsum, u0, __int_as_float(e0.y));
                j += 2;
            }

            acc.x += __shfl_xor_sync(0xffffffffu, acc.x, 16);
            acc.y += __shfl_xor_sync(0xffffffffu, acc.y, 16);
            acc.z += __shfl_xor_sync(0xffffffffu, acc.z, 16);
            acc.w += __shfl_xor_sync(0xffffffffu, acc.w, 16);
            dsum  += __shfl_xor_sync(0xffffffffu, dsum, 16);

            if (half == 0) {
                float inv = dsum > 0.f ? 1.f / dsum : 0.f;
                __half2 h0 = __floats2half2_rn(acc.x * inv, acc.y * inv);
                __half2 h1 = __floats2half2_rn(acc.z * inv, acc.w * inv);
                uint2 u;
                u.x = *(unsigned int*)&h0;
                u.y = *(unsigned int*)&h1;
                *(uint2*)&A_s[row * ASTRIDE + 64 + q * 4] = u;
            }
        }
    }

    __syncthreads();

    // GEMM: warp -> (m-tile r in 0..1, n-tile i in 0..7)
    {
        int r = warp & 1, i = warp >> 1;
        int g = lane >> 2, j = lane & 3;
        int arow = r * 16 + g;

        float c0 = 0.f, c1 = 0.f, c2 = 0.f, c3 = 0.f;
#pragma unroll
        for (int s = 0; s < 8; s++) {
            int k0 = 16 * s;
            unsigned a0 = *(const unsigned*)&A_s[arow * ASTRIDE + k0 + 2 * j];
            unsigned a1 = *(const unsigned*)&A_s[(arow + 8) * ASTRIDE + k0 + 2 * j];
            unsigned a2 = *(const unsigned*)&A_s[arow * ASTRIDE + k0 + 8 + 2 * j];
            unsigned a3 = *(const unsigned*)&A_s[(arow + 8) * ASTRIDE + k0 + 8 + 2 * j];
            unsigned b0 = *(const unsigned*)&W_s[(8 * i + g) * ASTRIDE + k0 + 2 * j];
            unsigned b1 = *(const unsigned*)&W_s[(8 * i + g) * ASTRIDE + k0 + 8 + 2 * j];
            mma16816(c0, c1, c2, c3, a0, a1, a2, a3, b0, b1);
        }

        int c = 8 * i + 2 * j;
        float2 bb = *(const float2*)&b_s[c];
        int n0 = base + arow;
        int n1 = n0 + 8;
        if (n0 < n) {
            float2 r0;
            r0.x = fmaxf(c0 + bb.x, 0.f);
            r0.y = fmaxf(c1 + bb.y, 0.f);
            *(float2*)&out[(size_t)n0 * 64 + c] = r0;
        }
        if (n1 < n) {
            float2 r1;
            r1.x = fmaxf(c2 + bb.x, 0.f);
            r1.y = fmaxf(c3 + bb.y, 0.f);
            *(float2*)&out[(size_t)n1 * 64 + c] = r1;
        }
    }
}

extern "C" void kernel_launch(void* const* d_in, const int* in_sizes, int n_in,
                              void* d_out, int out_size)
{
    const float* feature = (const float*)d_in[0];   // [N, 64]
    const float* attn_w  = (const float*)d_in[1];   // [128, 1]
    const float* lin_w   = (const float*)d_in[2];   // [64, 128]
    const float* lin_b   = (const float*)d_in[3];   // [64]
    const int*   src     = (const int*)d_in[4];     // [E]
    const int*   dst     = (const int*)d_in[5];     // [E]

    int n = in_sizes[0] / F;
    int E = in_sizes[4];

    const float4* feat4 = (const float4*)feature;

    {   // K1: scores + cnt reset + fp16 feature & W conversion
        int threads = 256;
        long long total = (long long)n * 4;
        int blocks = (int)((total + threads - 1) / threads);
        k_scores<<<blocks, threads>>>(feat4, attn_w, lin_w, n);
    }
    {   // K2: edge scatter
        int threads = 256;
        int blocks = (E + threads - 1) / threads;
        k_scatter<<<blocks, threads>>>(src, dst, E);
    }
    {   // K3: fused aggregation + output GEMM (32 nodes / 512-thread block)
        int blocks = (n + NPB - 1) / NPB;
        k_fused<<<blocks, FTHREADS>>>(lin_b, (float*)d_out, n);
    }
}

// round 15
// speedup vs baseline: 1.1700x; 1.0181x over previous
#include <cuda_runtime.h>
#include <cuda_fp16.h>
#include <math.h>

#define N_NODES_MAX 50000
#define F 64
#define NEG 0.01f
#define CAP 128
#define ASTRIDE 136   // halves per shared row: word stride 68 == 4 mod 32 banks

// ---- scratch ----
__device__ float  g_ssrc[N_NODES_MAX];
__device__ float  g_sdst[N_NODES_MAX];
__device__ int    g_cnt [N_NODES_MAX];
__device__ int    g_ebuf[N_NODES_MAX * CAP];  // src index only (4B entries)
__device__ __half g_AH[N_NODES_MAX * 128];    // fp16 feature rows (cols 0-63 used)
__device__ __half g_WH[64 * 128];             // fp16 copy of lin_w

// K1: node attention scores (4 threads/node) + zero cnt + fp16 feature copy
// + one-time fp16 W conversion (first 2048 global threads).
__global__ void k_scores(const float4* __restrict__ feat4,
                         const float*  __restrict__ attw,
                         const float*  __restrict__ lin_w,
                         int n)
{
    int t = blockIdx.x * blockDim.x + threadIdx.x;

    if (t < 2048) {   // convert W: 8192 floats = 2048 float4
        float4 w = __ldg((const float4*)&lin_w[t * 4]);
        __half2 h0 = __floats2half2_rn(w.x, w.y);
        __half2 h1 = __floats2half2_rn(w.z, w.w);
        uint2 u;
        u.x = *(unsigned int*)&h0;
        u.y = *(unsigned int*)&h1;
        *(uint2*)&g_WH[t * 4] = u;
    }

    int node = t >> 2;
    int p = t & 3;
    if (node >= n) return;

    float as = 0.f, ad = 0.f;
#pragma unroll
    for (int j = 0; j < 4; j++) {
        int q = p * 4 + j;
        float4 f = feat4[node * 16 + q];
        float4 wa = __ldg((const float4*)&attw[q * 4]);
        float4 wb = __ldg((const float4*)&attw[64 + q * 4]);
        as += f.x * wa.x + f.y * wa.y + f.z * wa.z + f.w * wa.w;
        ad += f.x * wb.x + f.y * wb.y + f.z * wb.z + f.w * wb.w;
        __half2 h0 = __floats2half2_rn(f.x, f.y);
        __half2 h1 = __floats2half2_rn(f.z, f.w);
        uint2 u;
        u.x = *(unsigned int*)&h0;
        u.y = *(unsigned int*)&h1;
        *(uint2*)&g_AH[node * 128 + q * 4] = u;
    }
    as += __shfl_xor_sync(0xffffffffu, as, 1);
    as += __shfl_xor_sync(0xffffffffu, as, 2);
    ad += __shfl_xor_sync(0xffffffffu, ad, 1);
    ad += __shfl_xor_sync(0xffffffffu, ad, 2);

    if (p == 0) {
        g_ssrc[node] = as;
        g_sdst[node] = ad;
        g_cnt[node]  = 0;
    }
}

// K2: minimal scatter — only the src index goes into the bucket.
// No score gathers, no exp here (moved to the aggregation side).
__global__ void k_scatter(const int* __restrict__ src,
                          const int* __restrict__ dst,
                          int E)
{
    int e = blockIdx.x * blockDim.x + threadIdx.x;
    if (e >= E) return;
    int s = src[e], d = dst[e];
    int slot = atomicAdd(&g_cnt[d], 1);
    if (slot < CAP)
        g_ebuf[d * CAP + slot] = s;
}

__device__ __forceinline__ float edge_w(int s, float sdn)
{
    float v = __ldg(&g_ssrc[s]) + sdn;   // uniform broadcast 4B load
    v = v > 0.f ? v : NEG * v;
    return __expf(v);
}

__device__ __forceinline__ void acc_one(float4& acc, float& dsum,
                                        uint2 u, float xw)
{
    float2 a = __half22float2(*(__half2*)&u.x);
    float2 b = __half22float2(*(__half2*)&u.y);
    acc.x += xw * a.x;
    acc.y += xw * a.y;
    acc.z += xw * b.x;
    acc.w += xw * b.y;
    dsum += xw;
}

// ---- HMMA m16n8k16 f16 x f16 -> f32 ----
__device__ __forceinline__ void mma16816(float& c0, float& c1, float& c2, float& c3,
                                         unsigned a0, unsigned a1, unsigned a2, unsigned a3,
                                         unsigned b0, unsigned b1)
{
    asm volatile("mma.sync.aligned.m16n8k16.row.col.f32.f16.f16.f32 "
                 "{%0,%1,%2,%3}, {%4,%5,%6,%7}, {%8,%9}, {%0,%1,%2,%3};"
                 : "+f"(c0), "+f"(c1), "+f"(c2), "+f"(c3)
                 : "r"(a0), "r"(a1), "r"(a2), "r"(a3), "r"(b0), "r"(b1));
}

// K3 (fused agg + output GEMM): 1024 threads = 32 warps per block, 64 nodes.
// Agg: R10 loop structure; entries are 4B src indices; edge weight
//   ex = exp(leaky(ssrc[s] + sdst[node])) computed in-loop (ssrc via
//   broadcast load issued parallel to the feature gather).
// GEMM: 32 warps each compute one m16n8k16 tile of h = relu(A @ W^T + b).
__global__ void __launch_bounds__(1024) k_fused(
                      const float* __restrict__ lin_b,
                      float*       __restrict__ out,     // [n, 64]
                      int n)
{
    __shared__ __align__(16) __half W_s[64 * ASTRIDE];
    __shared__ __align__(16) __half A_s[64 * ASTRIDE];
    __shared__ float b_s[64];

    int tid = threadIdx.x;
    int base = blockIdx.x * 64;

    // stage W (fp16, 16KB): 1024 threads x 1 uint4 (8 halves)
    {
        int o = tid >> 4, c = tid & 15;
        uint4 w = *(const uint4*)&g_WH[o * 128 + c * 8];
        *(uint4*)&W_s[o * ASTRIDE + c * 8] = w;
    }
    if (tid < 64) b_s[tid] = __ldg(&lin_b[tid]);
    // stage feature half of A tile: 64 rows x 8 uint4
    if (tid < 512) {
        int r = tid >> 3, c = tid & 7;
        int node = base + r;
        if (node >= n) node = n - 1;
        uint4 v = *(const uint4*)&g_AH[(size_t)node * 128 + c * 8];
        *(uint4*)&A_s[r * ASTRIDE + c * 8] = v;
    }

    int warp = tid >> 5, lane = tid & 31;
    int half = lane >> 4;
    int q = lane & 15;
    const uint2* ah = (const uint2*)g_AH;

#pragma unroll
    for (int pass = 0; pass < 2; pass++) {
        int row = warp + pass * 32;
        int node = base + row;
        if (node < n) {
            int deg = g_cnt[node];
            if (deg > CAP) deg = CAP;
            const int* eb = &g_ebuf[node * CAP];
            float sdn = g_sdst[node];

            float4 acc = make_float4(0.f, 0.f, 0.f, 0.f);
            float dsum = 0.f;

            int j = half;
            while (j + 6 < deg) {
                int s0 = __ldg(&eb[j]);
                int s1 = __ldg(&eb[j + 2]);
                int s2 = __ldg(&eb[j + 4]);
                int s3 = __ldg(&eb[j + 6]);
                uint2 u0 = ah[s0 * 32 + q];
                uint2 u1 = ah[s1 * 32 + q];
                uint2 u2 = ah[s2 * 32 + q];
                uint2 u3 = ah[s3 * 32 + q];
                float x0 = edge_w(s0, sdn);
                float x1 = edge_w(s1, sdn);
                float x2 = edge_w(s2, sdn);
                float x3 = edge_w(s3, sdn);
                acc_one(acc, dsum, u0, x0);
                acc_one(acc, dsum, u1, x1);
                acc_one(acc, dsum, u2, x2);
                acc_one(acc, dsum, u3, x3);
                j += 8;
            }
            while (j < deg) {
                int s0 = __ldg(&eb[j]);
                uint2 u0 = ah[s0 * 32 + q];
                acc_one(acc, dsum, u0, edge_w(s0, sdn));
                j += 2;
            }

            acc.x += __shfl_xor_sync(0xffffffffu, acc.x, 16);
            acc.y += __shfl_xor_sync(0xffffffffu, acc.y, 16);
            acc.z += __shfl_xor_sync(0xffffffffu, acc.z, 16);
            acc.w += __shfl_xor_sync(0xffffffffu, acc.w, 16);
            dsum  += __shfl_xor_sync(0xffffffffu, dsum, 16);

            if (half == 0) {
                float inv = dsum > 0.f ? 1.f / dsum : 0.f;
                __half2 h0 = __floats2half2_rn(acc.x * inv, acc.y * inv);
                __half2 h1 = __floats2half2_rn(acc.z * inv, acc.w * inv);
                uint2 u;
                u.x = *(unsigned int*)&h0;
                u.y = *(unsigned int*)&h1;
                *(uint2*)&A_s[row * ASTRIDE + 64 + q * 4] = u;
            }
        }
    }

    __syncthreads();

    // GEMM: warp -> (m-tile r, n-tile i)
    {
        int r = warp & 3, i = warp >> 2;
        int g = lane >> 2, j = lane & 3;
        int arow = r * 16 + g;

        float c0 = 0.f, c1 = 0.f, c2 = 0.f, c3 = 0.f;
#pragma unroll
        for (int s = 0; s < 8; s++) {
            int k0 = 16 * s;
            unsigned a0 = *(const unsigned*)&A_s[arow * ASTRIDE + k0 + 2 * j];
            unsigned a1 = *(const unsigned*)&A_s[(arow + 8) * ASTRIDE + k0 + 2 * j];
            unsigned a2 = *(const unsigned*)&A_s[arow * ASTRIDE + k0 + 8 + 2 * j];
            unsigned a3 = *(const unsigned*)&A_s[(arow + 8) * ASTRIDE + k0 + 8 + 2 * j];
            unsigned b0 = *(const unsigned*)&W_s[(8 * i + g) * ASTRIDE + k0 + 2 * j];
            unsigned b1 = *(const unsigned*)&W_s[(8 * i + g) * ASTRIDE + k0 + 8 + 2 * j];
            mma16816(c0, c1, c2, c3, a0, a1, a2, a3, b0, b1);
        }

        int c = 8 * i + 2 * j;
        float2 bb = *(const float2*)&b_s[c];
        int n0 = base + arow;
        int n1 = n0 + 8;
        if (n0 < n) {
            float2 r0;
            r0.x = fmaxf(c0 + bb.x, 0.f);
            r0.y = fmaxf(c1 + bb.y, 0.f);
            *(float2*)&out[(size_t)n0 * 64 + c] = r0;
        }
        if (n1 < n) {
            float2 r1;
            r1.x = fmaxf(c2 + bb.x, 0.f);
            r1.y = fmaxf(c3 + bb.y, 0.f);
            *(float2*)&out[(size_t)n1 * 64 + c] = r1;
        }
    }
}

extern "C" void kernel_launch(void* const* d_in, const int* in_sizes, int n_in,
                              void* d_out, int out_size)
{
    const float* feature = (const float*)d_in[0];   // [N, 64]
    const float* attn_w  = (const float*)d_in[1];   // [128, 1]
    const float* lin_w   = (const float*)d_in[2];   // [64, 128]
    const float* lin_b   = (const float*)d_in[3];   // [64]
    const int*   src     = (const int*)d_in[4];     // [E]
    const int*   dst     = (const int*)d_in[5];     // [E]

    int n = in_sizes[0] / F;
    int E = in_sizes[4];

    const float4* feat4 = (const float4*)feature;

    {   // K1: scores + cnt reset + fp16 feature & W conversion
        int threads = 256;
        long long total = (long long)n * 4;
        int blocks = (int)((total + threads - 1) / threads);
        k_scores<<<blocks, threads>>>(feat4, attn_w, lin_w, n);
    }
    {   // K2: minimal edge scatter (src index only)
        int threads = 256;
        int blocks = (E + threads - 1) / threads;
        k_scatter<<<blocks, threads>>>(src, dst, E);
    }
    {   // K3: fused aggregation + output GEMM (64 nodes / 1024-thread block)
        int blocks = (n + 63) / 64;
        k_fused<<<blocks, 1024>>>(lin_b, (float*)d_out, n);
    }
}

// round 16
// speedup vs baseline: 1.2601x; 1.0770x over previous
#include <cuda_runtime.h>
#include <cuda_fp16.h>
#include <math.h>

#define N_NODES_MAX 50000
#define F 64
#define NEG 0.01f
#define CAP 128
#define ASTRIDE 136   // halves per shared row: word stride 68 == 4 mod 32 banks

// ---- scratch ----
__device__ float  g_ssrc[N_NODES_MAX];
__device__ float  g_sdst[N_NODES_MAX];
__device__ int    g_cnt [N_NODES_MAX];
__device__ int2   g_ebuf[N_NODES_MAX * CAP];  // {src, __float_as_int(ex)}
__device__ __half g_AH[N_NODES_MAX * 128];    // fp16 feature rows (cols 0-63 used)
__device__ __half g_WH[64 * 128];             // fp16 copy of lin_w

// K1: node attention scores (2 threads/node, MLP 8) + zero cnt + fp16 feature
// copy + one-time fp16 W conversion (first 2048 global threads).
__global__ void k_scores(const float4* __restrict__ feat4,
                         const float*  __restrict__ attw,
                         const float*  __restrict__ lin_w,
                         int n)
{
    int t = blockIdx.x * blockDim.x + threadIdx.x;

    if (t < 2048) {   // convert W: 8192 floats = 2048 float4
        float4 w = __ldg((const float4*)&lin_w[t * 4]);
        __half2 h0 = __floats2half2_rn(w.x, w.y);
        __half2 h1 = __floats2half2_rn(w.z, w.w);
        uint2 u;
        u.x = *(unsigned int*)&h0;
        u.y = *(unsigned int*)&h1;
        *(uint2*)&g_WH[t * 4] = u;
    }

    int node = t >> 1;
    int p = t & 1;
    if (node >= n) return;

    float as = 0.f, ad = 0.f;
#pragma unroll
    for (int j = 0; j < 8; j++) {
        int q = p * 8 + j;
        float4 f = feat4[node * 16 + q];
        float4 wa = __ldg((const float4*)&attw[q * 4]);
        float4 wb = __ldg((const float4*)&attw[64 + q * 4]);
        as += f.x * wa.x + f.y * wa.y + f.z * wa.z + f.w * wa.w;
        ad += f.x * wb.x + f.y * wb.y + f.z * wb.z + f.w * wb.w;
        __half2 h0 = __floats2half2_rn(f.x, f.y);
        __half2 h1 = __floats2half2_rn(f.z, f.w);
        uint2 u;
        u.x = *(unsigned int*)&h0;
        u.y = *(unsigned int*)&h1;
        *(uint2*)&g_AH[node * 128 + q * 4] = u;
    }
    as += __shfl_xor_sync(0xffffffffu, as, 1);
    ad += __shfl_xor_sync(0xffffffffu, ad, 1);

    if (p == 0) {
        g_ssrc[node] = as;
        g_sdst[node] = ad;
        g_cnt[node]  = 0;
    }
}

// K2: per-edge exp score + bucket scatter (R10 form).
__global__ void k_scatter(const int* __restrict__ src,
                          const int* __restrict__ dst,
                          int E)
{
    int e = blockIdx.x * blockDim.x + threadIdx.x;
    if (e >= E) return;
    int s = src[e], d = dst[e];
    float v = g_ssrc[s] + g_sdst[d];
    v = v > 0.f ? v : NEG * v;
    float ex = __expf(v);
    int slot = atomicAdd(&g_cnt[d], 1);
    if (slot < CAP)
        g_ebuf[(size_t)d * CAP + slot] = make_int2(s, __float_as_int(ex));
}

__device__ __forceinline__ void acc_one(float4& acc, float& dsum,
                                        uint2 u, float xw)
{
    float2 a = __half22float2(*(__half2*)&u.x);
    float2 b = __half22float2(*(__half2*)&u.y);
    acc.x += xw * a.x;
    acc.y += xw * a.y;
    acc.z += xw * b.x;
    acc.w += xw * b.y;
    dsum += xw;
}

// ---- HMMA m16n8k16 f16 x f16 -> f32 ----
__device__ __forceinline__ void mma16816(float& c0, float& c1, float& c2, float& c3,
                                         unsigned a0, unsigned a1, unsigned a2, unsigned a3,
                                         unsigned b0, unsigned b1)
{
    asm volatile("mma.sync.aligned.m16n8k16.row.col.f32.f16.f16.f32 "
                 "{%0,%1,%2,%3}, {%4,%5,%6,%7}, {%8,%9}, {%0,%1,%2,%3};"
                 : "+f"(c0), "+f"(c1), "+f"(c2), "+f"(c3)
                 : "r"(a0), "r"(a1), "r"(a2), "r"(a3), "r"(b0), "r"(b1));
}

// K3 (fused agg + output GEMM): 1024 threads = 32 warps per block, 64 nodes.
// Agg: exact R10 loop, but bucket entries are pre-staged per warp into a
//   shared strip via coalesced loads (8 sectors per 32 edges instead of 32;
//   entry reads become 29-cyc LDS broadcasts instead of 250-cyc L2 loads).
// GEMM: 32 warps each compute one m16n8k16 tile of h = relu(A @ W^T + b).
// Dynamic smem: W (17.4KB) + A (17.4KB) + entry strips (32KB) ~= 67.5KB.
__global__ void __launch_bounds__(1024) k_fused(
                      const float* __restrict__ lin_b,
                      float*       __restrict__ out,     // [n, 64]
                      int n)
{
    extern __shared__ __align__(16) char shraw[];
    __half* W_s = (__half*)shraw;                 // 64 * ASTRIDE halves
    __half* A_s = W_s + 64 * ASTRIDE;             // 64 * ASTRIDE halves
    int2*   es_base = (int2*)(A_s + 64 * ASTRIDE);// 32 warps * CAP entries
    __shared__ float b_s[64];

    int tid = threadIdx.x;
    int base = blockIdx.x * 64;

    // stage W (fp16, 16KB): 1024 threads x 1 uint4 (8 halves)
    {
        int o = tid >> 4, c = tid & 15;
        uint4 w = *(const uint4*)&g_WH[o * 128 + c * 8];
        *(uint4*)&W_s[o * ASTRIDE + c * 8] = w;
    }
    if (tid < 64) b_s[tid] = __ldg(&lin_b[tid]);
    // stage feature half of A tile: 64 rows x 8 uint4
    if (tid < 512) {
        int r = tid >> 3, c = tid & 7;
        int node = base + r;
        if (node >= n) node = n - 1;
        uint4 v = *(const uint4*)&g_AH[(size_t)node * 128 + c * 8];
        *(uint4*)&A_s[r * ASTRIDE + c * 8] = v;
    }

    int warp = tid >> 5, lane = tid & 31;
    int half = lane >> 4;
    int q = lane & 15;
    const uint2* ah = (const uint2*)g_AH;
    int2* es = es_base + warp * CAP;

#pragma unroll
    for (int pass = 0; pass < 2; pass++) {
        int row = warp + pass * 32;
        int node = base + row;
        if (node < n) {
            int deg = g_cnt[node];
            if (deg > CAP) deg = CAP;
            const int2* eb = &g_ebuf[(size_t)node * CAP];

            // cooperative coalesced staging of this node's bucket entries
            __syncwarp();
            for (int w0 = lane; w0 < deg; w0 += 32)
                es[w0] = __ldg(&eb[w0]);
            __syncwarp();

            float4 acc = make_float4(0.f, 0.f, 0.f, 0.f);
            float dsum = 0.f;

            int j = half;
            while (j + 6 < deg) {
                int2 e0 = es[j];
                int2 e1 = es[j + 2];
                int2 e2 = es[j + 4];
                int2 e3 = es[j + 6];
                uint2 u0 = ah[e0.x * 32 + q];
                uint2 u1 = ah[e1.x * 32 + q];
                uint2 u2 = ah[e2.x * 32 + q];
                uint2 u3 = ah[e3.x * 32 + q];
                acc_one(acc, dsum, u0, __int_as_float(e0.y));
                acc_one(acc, dsum, u1, __int_as_float(e1.y));
                acc_one(acc, dsum, u2, __int_as_float(e2.y));
                acc_one(acc, dsum, u3, __int_as_float(e3.y));
                j += 8;
            }
            while (j < deg) {
                int2 e0 = es[j];
                uint2 u0 = ah[e0.x * 32 + q];
                acc_one(acc, dsum, u0, __int_as_float(e0.y));
                j += 2;
            }

            acc.x += __shfl_xor_sync(0xffffffffu, acc.x, 16);
            acc.y += __shfl_xor_sync(0xffffffffu, acc.y, 16);
            acc.z += __shfl_xor_sync(0xffffffffu, acc.z, 16);
            acc.w += __shfl_xor_sync(0xffffffffu, acc.w, 16);
            dsum  += __shfl_xor_sync(0xffffffffu, dsum, 16);

            if (half == 0) {
                float inv = dsum > 0.f ? 1.f / dsum : 0.f;
                __half2 h0 = __floats2half2_rn(acc.x * inv, acc.y * inv);
                __half2 h1 = __floats2half2_rn(acc.z * inv, acc.w * inv);
                uint2 u;
                u.x = *(unsigned int*)&h0;
                u.y = *(unsigned int*)&h1;
                *(uint2*)&A_s[row * ASTRIDE + 64 + q * 4] = u;
            }
        }
    }

    __syncthreads();

    // GEMM: warp -> (m-tile r, n-tile i)
    {
        int r = warp & 3, i = warp >> 2;
        int g = lane >> 2, j = lane & 3;
        int arow = r * 16 + g;

        float c0 = 0.f, c1 = 0.f, c2 = 0.f, c3 = 0.f;
#pragma unroll
        for (int s = 0; s < 8; s++) {
            int k0 = 16 * s;
            unsigned a0 = *(const unsigned*)&A_s[arow * ASTRIDE + k0 + 2 * j];
            unsigned a1 = *(const unsigned*)&A_s[(arow + 8) * ASTRIDE + k0 + 2 * j];
            unsigned a2 = *(const unsigned*)&A_s[arow * ASTRIDE + k0 + 8 + 2 * j];
            unsigned a3 = *(const unsigned*)&A_s[(arow + 8) * ASTRIDE + k0 + 8 + 2 * j];
            unsigned b0 = *(const unsigned*)&W_s[(8 * i + g) * ASTRIDE + k0 + 2 * j];
            unsigned b1 = *(const unsigned*)&W_s[(8 * i + g) * ASTRIDE + k0 + 8 + 2 * j];
            mma16816(c0, c1, c2, c3, a0, a1, a2, a3, b0, b1);
        }

        int c = 8 * i + 2 * j;
        float2 bb = *(const float2*)&b_s[c];
        int n0 = base + arow;
        int n1 = n0 + 8;
        if (n0 < n) {
            float2 r0;
            r0.x = fmaxf(c0 + bb.x, 0.f);
            r0.y = fmaxf(c1 + bb.y, 0.f);
            *(float2*)&out[(size_t)n0 * 64 + c] = r0;
        }
        if (n1 < n) {
            float2 r1;
            r1.x = fmaxf(c2 + bb.x, 0.f);
            r1.y = fmaxf(c3 + bb.y, 0.f);
            *(float2*)&out[(size_t)n1 * 64 + c] = r1;
        }
    }
}

extern "C" void kernel_launch(void* const* d_in, const int* in_sizes, int n_in,
                              void* d_out, int out_size)
{
    const float* feature = (const float*)d_in[0];   // [N, 64]
    const float* attn_w  = (const float*)d_in[1];   // [128, 1]
    const float* lin_w   = (const float*)d_in[2];   // [64, 128]
    const float* lin_b   = (const float*)d_in[3];   // [64]
    const int*   src     = (const int*)d_in[4];     // [E]
    const int*   dst     = (const int*)d_in[5];     // [E]

    int n = in_sizes[0] / F;
    int E = in_sizes[4];

    const float4* feat4 = (const float4*)feature;

    {   // K1: scores (2 threads/node) + cnt reset + fp16 feature & W conv
        int threads = 256;
        long long total = (long long)n * 2;
        int blocks = (int)((total + threads - 1) / threads);
        k_scores<<<blocks, threads>>>(feat4, attn_w, lin_w, n);
    }
    {   // K2: edge scatter
        int threads = 256;
        int blocks = (E + threads - 1) / threads;
        k_scatter<<<blocks, threads>>>(src, dst, E);
    }
    {   // K3: fused aggregation + output GEMM (64 nodes / 1024-thread block)
        size_t shbytes = (size_t)(2 * 64 * ASTRIDE) * sizeof(__half)
                       + (size_t)32 * CAP * sizeof(int2);
        static int attr_done = 0;
        if (!attr_done) {
            cudaFuncSetAttribute(k_fused, cudaFuncAttributeMaxDynamicSharedMemorySize,
                                 (int)shbytes);
            attr_done = 1;
        }
        int blocks = (n + 63) / 64;
        k_fused<<<blocks, 1024, shbytes>>>(lin_b, (float*)d_out, n);
    }
}

// round 17
// speedup vs baseline: 1.3018x; 1.0331x over previous
#include <cuda_runtime.h>
#include <cuda_fp16.h>
#include <math.h>

#define N_NODES_MAX 50000
#define F 64
#define NEG 0.01f
#define CAP 128
#define ASTRIDE 136   // halves per shared row: word stride 68 == 4 mod 32 banks

// ---- scratch ----
__device__ float  g_ssrc[N_NODES_MAX];
__device__ float  g_sdst[N_NODES_MAX];
__device__ int    g_cnt [N_NODES_MAX];
__device__ int2   g_ebuf[N_NODES_MAX * CAP];  // {src, __float_as_int(ex)}
__device__ __half g_AH[N_NODES_MAX * 128];    // fp16 feature rows (cols 0-63 used)
__device__ __half g_WH[64 * 128];             // fp16 copy of lin_w

// K1: node attention scores (4 threads/node) + zero cnt + fp16 feature copy
// + one-time fp16 W conversion (first 2048 global threads).
__global__ void k_scores(const float4* __restrict__ feat4,
                         const float*  __restrict__ attw,
                         const float*  __restrict__ lin_w,
                         int n)
{
    int t = blockIdx.x * blockDim.x + threadIdx.x;

    if (t < 2048) {   // convert W: 8192 floats = 2048 float4
        float4 w = __ldg((const float4*)&lin_w[t * 4]);
        __half2 h0 = __floats2half2_rn(w.x, w.y);
        __half2 h1 = __floats2half2_rn(w.z, w.w);
        uint2 u;
        u.x = *(unsigned int*)&h0;
        u.y = *(unsigned int*)&h1;
        *(uint2*)&g_WH[t * 4] = u;
    }

    int node = t >> 2;
    int p = t & 3;
    if (node >= n) return;

    float as = 0.f, ad = 0.f;
#pragma unroll
    for (int j = 0; j < 4; j++) {
        int q = p * 4 + j;
        float4 f = feat4[node * 16 + q];
        float4 wa = __ldg((const float4*)&attw[q * 4]);
        float4 wb = __ldg((const float4*)&attw[64 + q * 4]);
        as += f.x * wa.x + f.y * wa.y + f.z * wa.z + f.w * wa.w;
        ad += f.x * wb.x + f.y * wb.y + f.z * wb.z + f.w * wb.w;
        __half2 h0 = __floats2half2_rn(f.x, f.y);
        __half2 h1 = __floats2half2_rn(f.z, f.w);
        uint2 u;
        u.x = *(unsigned int*)&h0;
        u.y = *(unsigned int*)&h1;
        *(uint2*)&g_AH[node * 128 + q * 4] = u;
    }
    as += __shfl_xor_sync(0xffffffffu, as, 1);
    as += __shfl_xor_sync(0xffffffffu, as, 2);
    ad += __shfl_xor_sync(0xffffffffu, ad, 1);
    ad += __shfl_xor_sync(0xffffffffu, ad, 2);

    if (p == 0) {
        g_ssrc[node] = as;
        g_sdst[node] = ad;
        g_cnt[node]  = 0;
    }
}

// K2: per-edge exp score + bucket scatter.
__global__ void k_scatter(const int* __restrict__ src,
                          const int* __restrict__ dst,
                          int E)
{
    int e = blockIdx.x * blockDim.x + threadIdx.x;
    if (e >= E) return;
    int s = src[e], d = dst[e];
    float v = g_ssrc[s] + g_sdst[d];
    v = v > 0.f ? v : NEG * v;
    float ex = __expf(v);
    int slot = atomicAdd(&g_cnt[d], 1);
    if (slot < CAP)
        g_ebuf[(size_t)d * CAP + slot] = make_int2(s, __float_as_int(ex));
}

__device__ __forceinline__ void acc_one(float4& acc, float& dsum,
                                        uint2 u, float xw)
{
    float2 a = __half22float2(*(__half2*)&u.x);
    float2 b = __half22float2(*(__half2*)&u.y);
    acc.x += xw * a.x;
    acc.y += xw * a.y;
    acc.z += xw * b.x;
    acc.w += xw * b.y;
    dsum += xw;
}

// ---- HMMA m16n8k16 f16 x f16 -> f32 ----
__device__ __forceinline__ void mma16816(float& c0, float& c1, float& c2, float& c3,
                                         unsigned a0, unsigned a1, unsigned a2, unsigned a3,
                                         unsigned b0, unsigned b1)
{
    asm volatile("mma.sync.aligned.m16n8k16.row.col.f32.f16.f16.f32 "
                 "{%0,%1,%2,%3}, {%4,%5,%6,%7}, {%8,%9}, {%0,%1,%2,%3};"
                 : "+f"(c0), "+f"(c1), "+f"(c2), "+f"(c3)
                 : "r"(a0), "r"(a1), "r"(a2), "r"(a3), "r"(b0), "r"(b1));
}

// K3 (fused agg + output GEMM): 1024 threads = 32 warps per block, 64 nodes.
// Agg: exact R10 loop; bucket entries pre-staged per warp into a shared
//   strip via coalesced loads (entry reads become LDS broadcasts).
// GEMM: 32 warps each compute one m16n8k16 tile of h = relu(A @ W^T + b).
// Dynamic smem: W (17.4KB) + A (17.4KB) + entry strips (32KB) ~= 67.5KB.
__global__ void __launch_bounds__(1024) k_fused(
                      const float* __restrict__ lin_b,
                      float*       __restrict__ out,     // [n, 64]
                      int n)
{
    extern __shared__ __align__(16) char shraw[];
    __half* W_s = (__half*)shraw;                 // 64 * ASTRIDE halves
    __half* A_s = W_s + 64 * ASTRIDE;             // 64 * ASTRIDE halves
    int2*   es_base = (int2*)(A_s + 64 * ASTRIDE);// 32 warps * CAP entries
    __shared__ float b_s[64];

    int tid = threadIdx.x;
    int base = blockIdx.x * 64;

    // stage W (fp16, 16KB): 1024 threads x 1 uint4 (8 halves)
    {
        int o = tid >> 4, c = tid & 15;
        uint4 w = *(const uint4*)&g_WH[o * 128 + c * 8];
        *(uint4*)&W_s[o * ASTRIDE + c * 8] = w;
    }
    if (tid < 64) b_s[tid] = __ldg(&lin_b[tid]);
    // stage feature half of A tile: 64 rows x 8 uint4
    if (tid < 512) {
        int r = tid >> 3, c = tid & 7;
        int node = base + r;
        if (node >= n) node = n - 1;
        uint4 v = *(const uint4*)&g_AH[(size_t)node * 128 + c * 8];
        *(uint4*)&A_s[r * ASTRIDE + c * 8] = v;
    }

    int warp = tid >> 5, lane = tid & 31;
    int half = lane >> 4;
    int q = lane & 15;
    const uint2* ah = (const uint2*)g_AH;
    int2* es = es_base + warp * CAP;

#pragma unroll
    for (int pass = 0; pass < 2; pass++) {
        int row = warp + pass * 32;
        int node = base + row;
        if (node < n) {
            int deg = g_cnt[node];
            if (deg > CAP) deg = CAP;
            const int2* eb = &g_ebuf[(size_t)node * CAP];

            // cooperative coalesced staging of this node's bucket entries
            __syncwarp();
            for (int w0 = lane; w0 < deg; w0 += 32)
                es[w0] = __ldg(&eb[w0]);
            __syncwarp();

            float4 acc = make_float4(0.f, 0.f, 0.f, 0.f);
            float dsum = 0.f;

            int j = half;
            while (j + 6 < deg) {
                int2 e0 = es[j];
                int2 e1 = es[j + 2];
                int2 e2 = es[j + 4];
                int2 e3 = es[j + 6];
                uint2 u0 = ah[e0.x * 32 + q];
                uint2 u1 = ah[e1.x * 32 + q];
                uint2 u2 = ah[e2.x * 32 + q];
                uint2 u3 = ah[e3.x * 32 + q];
                acc_one(acc, dsum, u0, __int_as_float(e0.y));
                acc_one(acc, dsum, u1, __int_as_float(e1.y));
                acc_one(acc, dsum, u2, __int_as_float(e2.y));
                acc_one(acc, dsum, u3, __int_as_float(e3.y));
                j += 8;
            }
            while (j < deg) {
                int2 e0 = es[j];
                uint2 u0 = ah[e0.x * 32 + q];
                acc_one(acc, dsum, u0, __int_as_float(e0.y));
                j += 2;
            }

            acc.x += __shfl_xor_sync(0xffffffffu, acc.x, 16);
            acc.y += __shfl_xor_sync(0xffffffffu, acc.y, 16);
            acc.z += __shfl_xor_sync(0xffffffffu, acc.z, 16);
            acc.w += __shfl_xor_sync(0xffffffffu, acc.w, 16);
            dsum  += __shfl_xor_sync(0xffffffffu, dsum, 16);

            if (half == 0) {
                float inv = dsum > 0.f ? 1.f / dsum : 0.f;
                __half2 h0 = __floats2half2_rn(acc.x * inv, acc.y * inv);
                __half2 h1 = __floats2half2_rn(acc.z * inv, acc.w * inv);
                uint2 u;
                u.x = *(unsigned int*)&h0;
                u.y = *(unsigned int*)&h1;
                *(uint2*)&A_s[row * ASTRIDE + 64 + q * 4] = u;
            }
        }
    }

    __syncthreads();

    // GEMM: warp -> (m-tile r, n-tile i)
    {
        int r = warp & 3, i = warp >> 2;
        int g = lane >> 2, j = lane & 3;
        int arow = r * 16 + g;

        float c0 = 0.f, c1 = 0.f, c2 = 0.f, c3 = 0.f;
#pragma unroll
        for (int s = 0; s < 8; s++) {
            int k0 = 16 * s;
            unsigned a0 = *(const unsigned*)&A_s[arow * ASTRIDE + k0 + 2 * j];
            unsigned a1 = *(const unsigned*)&A_s[(arow + 8) * ASTRIDE + k0 + 2 * j];
            unsigned a2 = *(const unsigned*)&A_s[arow * ASTRIDE + k0 + 8 + 2 * j];
            unsigned a3 = *(const unsigned*)&A_s[(arow + 8) * ASTRIDE + k0 + 8 + 2 * j];
            unsigned b0 = *(const unsigned*)&W_s[(8 * i + g) * ASTRIDE + k0 + 2 * j];
            unsigned b1 = *(const unsigned*)&W_s[(8 * i + g) * ASTRIDE + k0 + 8 + 2 * j];
            mma16816(c0, c1, c2, c3, a0, a1, a2, a3, b0, b1);
        }

        int c = 8 * i + 2 * j;
        float2 bb = *(const float2*)&b_s[c];
        int n0 = base + arow;
        int n1 = n0 + 8;
        if (n0 < n) {
            float2 r0;
            r0.x = fmaxf(c0 + bb.x, 0.f);
            r0.y = fmaxf(c1 + bb.y, 0.f);
            *(float2*)&out[(size_t)n0 * 64 + c] = r0;
        }
        if (n1 < n) {
            float2 r1;
            r1.x = fmaxf(c2 + bb.x, 0.f);
            r1.y = fmaxf(c3 + bb.y, 0.f);
            *(float2*)&out[(size_t)n1 * 64 + c] = r1;
        }
    }
}

extern "C" void kernel_launch(void* const* d_in, const int* in_sizes, int n_in,
                              void* d_out, int out_size)
{
    const float* feature = (const float*)d_in[0];   // [N, 64]
    const float* attn_w  = (const float*)d_in[1];   // [128, 1]
    const float* lin_w   = (const float*)d_in[2];   // [64, 128]
    const float* lin_b   = (const float*)d_in[3];   // [64]
    const int*   src     = (const int*)d_in[4];     // [E]
    const int*   dst     = (const int*)d_in[5];     // [E]

    int n = in_sizes[0] / F;
    int E = in_sizes[4];

    const float4* feat4 = (const float4*)feature;

    {   // K1: scores (4 threads/node) + cnt reset + fp16 feature & W conv
        int threads = 256;
        long long total = (long long)n * 4;
        int blocks = (int)((total + threads - 1) / threads);
        k_scores<<<blocks, threads>>>(feat4, attn_w, lin_w, n);
    }
    {   // K2: edge scatter
        int threads = 256;
        int blocks = (E + threads - 1) / threads;
        k_scatter<<<blocks, threads>>>(src, dst, E);
    }
    {   // K3: fused aggregation + output GEMM (64 nodes / 1024-thread block)
        size_t shbytes = (size_t)(2 * 64 * ASTRIDE) * sizeof(__half)
                       + (size_t)32 * CAP * sizeof(int2);
        static int attr_done = 0;
        if (!attr_done) {
            cudaFuncSetAttribute(k_fused, cudaFuncAttributeMaxDynamicSharedMemorySize,
                                 (int)shbytes);
            attr_done = 1;
        }
        int blocks = (n + 63) / 64;
        k_fused<<<blocks, 1024, shbytes>>>(lin_b, (float*)d_out, n);
    }
}